// round 1
// baseline (speedup 1.0000x reference)
#include <cuda_runtime.h>
#include <cuda_bf16.h>

// Problem constants (from reference setup_inputs)
#define BB 8
#define NN 2048
#define CIN 64
#define CC 128
#define KK 16
#define FF 512
#define NP (BB*NN)          // 16384 points

// ---------------- scratch (device globals; no cudaMalloc allowed) -----------
__device__ float g_h   [NP*CC];
__device__ float g_hn  [NP*CC];
__device__ float g_qa  [NP*CC];
__device__ float g_ka  [NP*CC];
__device__ float g_v   [NP*CC];
__device__ float g_hnew[NP*CC];
__device__ float g_h2  [NP*CC];
__device__ float g_t512[NP*FF];
__device__ int   g_idx [NP*KK];

__device__ float g_WinT[CIN*CC];      // [c][o]
__device__ float g_Wd2T[CC*CC];       // [c][o]
__device__ float g_WvT [CC*CC];       // [c][o]
__device__ float g_WaqT[CC*CC];       // (Wa@Wq) transposed: [c][o]
__device__ float g_WakT[CC*CC];       // (Wa@Wk) transposed
__device__ float g_WadT[CC*CC];       // (Wa@Wd2) transposed
__device__ float g_cd  [CC];          // Wa@bd2 + ba
__device__ float g_Wf1T[CC*FF];       // [c][r]
__device__ float g_Wf2T[FF*CC];       // [r][o]

// ---------------- f32x2 packed helpers --------------------------------------
__device__ __forceinline__ unsigned long long pack2(float x){
    unsigned long long r;
    asm("mov.b64 %0, {%1, %1};" : "=l"(r) : "f"(x));
    return r;
}
__device__ __forceinline__ void fma2(unsigned long long &a, unsigned long long b, unsigned long long c){
    asm("fma.rn.f32x2 %0, %1, %2, %0;" : "+l"(a) : "l"(b), "l"(c));
}
__device__ __forceinline__ float2 unpack2(unsigned long long v){
    float2 f;
    asm("mov.b64 {%0, %1}, %2;" : "=f"(f.x), "=f"(f.y) : "l"(v));
    return f;
}

// ---------------- prep: transposes ------------------------------------------
__global__ void k_prep_tr(const float* __restrict__ Win, const float* __restrict__ Wd2,
                          const float* __restrict__ Wv,  const float* __restrict__ Wf1,
                          const float* __restrict__ Wf2){
    int i = blockIdx.x*blockDim.x + threadIdx.x;   // 0..65535
    if (i < CIN*CC){ int c=i>>7, o=i&127; g_WinT[i] = Win[o*CIN+c]; }
    if (i < CC*CC){  int c=i>>7, o=i&127; g_Wd2T[i] = Wd2[o*CC+c]; g_WvT[i] = Wv[o*CC+c]; }
    if (i < CC*FF){  int c=i>>9, r=i&511; g_Wf1T[i] = Wf1[r*CC+c]; }
    if (i < FF*CC){  int r=i>>7, o=i&127; g_Wf2T[i] = Wf2[o*FF+r]; }
}

// ---------------- prep: combined weights (Wa@Wq etc.), stored transposed ----
__global__ void k_prep_combo(const float* __restrict__ Wa, const float* __restrict__ Wq,
                             const float* __restrict__ Wk, const float* __restrict__ Wd2){
    int o = blockIdx.x;          // 0..127
    int c = threadIdx.x;         // 0..127
    const float* src = (blockIdx.y==0)?Wq : (blockIdx.y==1)?Wk : Wd2;
    float* dst       = (blockIdx.y==0)?g_WaqT : (blockIdx.y==1)?g_WakT : g_WadT;
    float acc = 0.f;
    #pragma unroll 4
    for (int m=0; m<CC; m++) acc = fmaf(Wa[o*CC+m], src[m*CC+c], acc);
    dst[c*CC+o] = acc;
}

__global__ void k_prep_cd(const float* __restrict__ Wa, const float* __restrict__ bd2,
                          const float* __restrict__ ba){
    int o = threadIdx.x;
    float acc = ba[o];
    #pragma unroll 4
    for (int c=0;c<CC;c++) acc = fmaf(Wa[o*CC+c], bd2[c], acc);
    g_cd[o] = acc;
}

// ---------------- in_proj: h = Win @ x + bin  (16 points per block) ---------
__global__ void __launch_bounds__(128) k_inproj(const float* __restrict__ x,
                                                const float* __restrict__ binv){
    __shared__ float xs[CIN][16];
    int blk = blockIdx.x;                 // 0..1023
    int b   = blk >> 7;                   // 128 blocks per batch
    int n0  = (blk & 127) << 4;
    int pt0 = b*NN + n0;
    int tid = threadIdx.x;
    const float* xb = x + (size_t)b*CIN*NN;
    for (int f=tid; f<CIN*16; f+=128){ int c=f>>4, m=f&15; xs[c][m] = xb[c*NN + n0 + m]; }
    __syncthreads();
    float acc[16];
    #pragma unroll
    for (int m=0;m<16;m++) acc[m]=0.f;
    #pragma unroll 2
    for (int c=0;c<CIN;c++){
        float w = g_WinT[c*CC + tid];
        const float4* xp = (const float4*)xs[c];
        float4 v0=xp[0], v1=xp[1], v2=xp[2], v3=xp[3];
        float hv[16] = {v0.x,v0.y,v0.z,v0.w, v1.x,v1.y,v1.z,v1.w,
                        v2.x,v2.y,v2.z,v2.w, v3.x,v3.y,v3.z,v3.w};
        #pragma unroll
        for (int m=0;m<16;m++) acc[m] = fmaf(w, hv[m], acc[m]);
    }
    float bo = binv[tid];
    #pragma unroll
    for (int m=0;m<16;m++) g_h[(size_t)(pt0+m)*CC + tid] = acc[m] + bo;
}

// ---------------- LayerNorm over channels (block per point) -----------------
__global__ void __launch_bounds__(128) k_ln(const float* __restrict__ in, float* __restrict__ out,
                                            const float* __restrict__ g, const float* __restrict__ bbv){
    __shared__ float ws[4];
    int pt = blockIdx.x, t = threadIdx.x;
    float v = in[(size_t)pt*CC + t];
    float s = v;
    #pragma unroll
    for (int o=16;o;o>>=1) s += __shfl_xor_sync(0xffffffffu, s, o);
    if ((t&31)==0) ws[t>>5] = s;
    __syncthreads();
    float mu = (ws[0]+ws[1]+ws[2]+ws[3]) * (1.f/CC);
    float dv = v - mu;
    __syncthreads();
    float q = dv*dv;
    #pragma unroll
    for (int o=16;o;o>>=1) q += __shfl_xor_sync(0xffffffffu, q, o);
    if ((t&31)==0) ws[t>>5] = q;
    __syncthreads();
    float var = (ws[0]+ws[1]+ws[2]+ws[3]) * (1.f/CC);
    out[(size_t)pt*CC + t] = dv * rsqrtf(var + 1e-5f) * g[t] + bbv[t];
}

// ---------------- KNN: top-16 nearest (block per point) ---------------------
__global__ void __launch_bounds__(256) k_knn(const float* __restrict__ p, int* __restrict__ idx_out){
    __shared__ float px[NN], py[NN], pz[NN], sc[NN];
    __shared__ float sval[8]; __shared__ int sidx[8];
    int b = blockIdx.x >> 11, n = blockIdx.x & (NN-1);
    int tid = threadIdx.x;
    const float* pb = p + (size_t)b*3*NN;
    for (int i=tid;i<NN;i+=256){ px[i]=pb[i]; py[i]=pb[NN+i]; pz[i]=pb[2*NN+i]; }
    __syncthreads();
    float qx=px[n], qy=py[n], qz=pz[n];
    float xxq = qx*qx + qy*qy + qz*qz;
    for (int i=tid;i<NN;i+=256){
        float inner = qx*px[i] + qy*py[i] + qz*pz[i];
        float xxj   = px[i]*px[i] + py[i]*py[i] + pz[i]*pz[i];
        float s = 2.f*inner - xxq - xxj;       // = -||pi-pj||^2
        sc[i] = (i==n) ? -1e9f : s;
    }
    __syncthreads();
    int lane = tid & 31, warp = tid >> 5;
    for (int r=0;r<KK;r++){
        float bv = -3.4e38f; int bi = 0;
        for (int i=tid;i<NN;i+=256){ float v=sc[i]; if (v>bv){ bv=v; bi=i; } }
        #pragma unroll
        for (int o=16;o;o>>=1){
            float v2 = __shfl_xor_sync(0xffffffffu, bv, o);
            int   i2 = __shfl_xor_sync(0xffffffffu, bi, o);
            if (v2>bv || (v2==bv && i2<bi)){ bv=v2; bi=i2; }
        }
        if (lane==0){ sval[warp]=bv; sidx[warp]=bi; }
        __syncthreads();
        if (tid==0){
            float mv = sval[0]; int mi = sidx[0];
            #pragma unroll
            for (int w=1;w<8;w++){
                float v2=sval[w]; int i2=sidx[w];
                if (v2>mv || (v2==mv && i2<mi)){ mv=v2; mi=i2; }
            }
            idx_out[((size_t)b*NN+n)*KK + r] = mi;
            sc[mi] = -3.4e38f;
        }
        __syncthreads();
    }
}

// ---------------- projections: qa = hn@(WaWq)^T, ka = hn@(WaWk)^T, v = hn@Wv^T
__global__ void __launch_bounds__(128) k_proj(){
    __shared__ float hs[CC][16];
    int pt0 = blockIdx.x * 16;
    int tid = threadIdx.x;
    for (int f=tid; f<CC*16; f+=128) hs[f&127][f>>7] = g_hn[(size_t)pt0*CC + f];
    __syncthreads();
    float aq[16], ak[16], av[16];
    #pragma unroll
    for (int m=0;m<16;m++){ aq[m]=0.f; ak[m]=0.f; av[m]=0.f; }
    for (int c=0;c<CC;c++){
        float wq = g_WaqT[c*CC+tid];
        float wk = g_WakT[c*CC+tid];
        float wv = g_WvT [c*CC+tid];
        const float4* hp = (const float4*)hs[c];
        float4 v0=hp[0], v1=hp[1], v2=hp[2], v3=hp[3];
        float hv[16] = {v0.x,v0.y,v0.z,v0.w, v1.x,v1.y,v1.z,v1.w,
                        v2.x,v2.y,v2.z,v2.w, v3.x,v3.y,v3.z,v3.w};
        #pragma unroll
        for (int m=0;m<16;m++){
            aq[m] = fmaf(wq, hv[m], aq[m]);
            ak[m] = fmaf(wk, hv[m], ak[m]);
            av[m] = fmaf(wv, hv[m], av[m]);
        }
    }
    #pragma unroll
    for (int m=0;m<16;m++){
        size_t base = (size_t)(pt0+m)*CC + tid;
        g_qa[base]=aq[m]; g_ka[base]=ak[m]; g_v[base]=av[m];
    }
}

// ---------------- attention core (block per point, thread per channel) ------
__global__ void __launch_bounds__(128) k_attn(const float* __restrict__ p,
                                              const float* __restrict__ Wd1,
                                              const float* __restrict__ bd1,
                                              const float* __restrict__ bd2v){
    __shared__ float t_s[CC][16];
    __shared__ float rel_s[KK][3];
    __shared__ int   idxs[KK];
    int pt = blockIdx.x;
    int b  = pt >> 11;
    int n  = pt & (NN-1);
    int tid = threadIdx.x;
    if (tid < KK){
        int jn = g_idx[(size_t)pt*KK + tid];
        idxs[tid] = jn;
        const float* pb = p + (size_t)b*3*NN;
        rel_s[tid][0] = pb[n]        - pb[jn];
        rel_s[tid][1] = pb[NN+n]     - pb[NN+jn];
        rel_s[tid][2] = pb[2*NN+n]   - pb[2*NN+jn];
    }
    __syncthreads();
    {   // t_j[c] = relu(Wd1[c,:]·rel_j + bd1[c])
        float w0=Wd1[tid*3], w1=Wd1[tid*3+1], w2=Wd1[tid*3+2], bb=bd1[tid];
        #pragma unroll
        for (int j=0;j<KK;j++){
            float t = fmaf(w0, rel_s[j][0], fmaf(w1, rel_s[j][1], fmaf(w2, rel_s[j][2], bb)));
            t_s[tid][j] = fmaxf(t, 0.f);
        }
    }
    __syncthreads();
    unsigned long long dacc[8], lacc[8];
    #pragma unroll
    for (int i=0;i<8;i++){ dacc[i]=0ull; lacc[i]=0ull; }
    const float* wdp = g_Wd2T + tid;
    const float* wap = g_WadT + tid;
    #pragma unroll 2
    for (int c=0;c<CC;c++){
        unsigned long long wd2 = pack2(wdp[c*CC]);
        unsigned long long wa2 = pack2(wap[c*CC]);
        const ulonglong2* tp = (const ulonglong2*)t_s[c];
        ulonglong2 q0=tp[0], q1=tp[1], q2=tp[2], q3=tp[3];
        fma2(dacc[0],wd2,q0.x); fma2(dacc[1],wd2,q0.y);
        fma2(dacc[2],wd2,q1.x); fma2(dacc[3],wd2,q1.y);
        fma2(dacc[4],wd2,q2.x); fma2(dacc[5],wd2,q2.y);
        fma2(dacc[6],wd2,q3.x); fma2(dacc[7],wd2,q3.y);
        fma2(lacc[0],wa2,q0.x); fma2(lacc[1],wa2,q0.y);
        fma2(lacc[2],wa2,q1.x); fma2(lacc[3],wa2,q1.y);
        fma2(lacc[4],wa2,q2.x); fma2(lacc[5],wa2,q2.y);
        fma2(lacc[6],wa2,q3.x); fma2(lacc[7],wa2,q3.y);
    }
    float d[KK], l[KK];
    #pragma unroll
    for (int i=0;i<8;i++){
        float2 fd = unpack2(dacc[i]); d[2*i]=fd.x; d[2*i+1]=fd.y;
        float2 fl = unpack2(lacc[i]); l[2*i]=fl.x; l[2*i+1]=fl.y;
    }
    float bd2o = bd2v[tid];
    float base = g_qa[(size_t)pt*CC + tid] + g_cd[tid];
    float mx = -3.4e38f;
    #pragma unroll
    for (int j=0;j<KK;j++){
        l[j] += base - g_ka[((size_t)b*NN + idxs[j])*CC + tid];
        d[j] += bd2o;
        mx = fmaxf(mx, l[j]);
    }
    float s = 0.f;
    #pragma unroll
    for (int j=0;j<KK;j++){ l[j] = __expf(l[j]-mx); s += l[j]; }
    float y = 0.f;
    #pragma unroll
    for (int j=0;j<KK;j++){
        float vj = g_v[((size_t)b*NN + idxs[j])*CC + tid];
        y = fmaf(l[j], vj + d[j], y);
    }
    y /= s;
    g_hnew[(size_t)pt*CC + tid] = g_h[(size_t)pt*CC + tid] + y;
}

// ---------------- FFN stage 1: t = relu(h2 @ Wf1^T + bf1) -------------------
__global__ void __launch_bounds__(256) k_ffn1(const float* __restrict__ bf1){
    __shared__ float hs[CC][16];
    int pt0 = blockIdx.x * 16;
    int tid = threadIdx.x;
    for (int f=tid; f<CC*16; f+=256) hs[f&127][f>>7] = g_h2[(size_t)pt0*CC + f];
    __syncthreads();
    float a0[16], a1[16];
    #pragma unroll
    for (int m=0;m<16;m++){ a0[m]=0.f; a1[m]=0.f; }
    for (int c=0;c<CC;c++){
        float w0 = g_Wf1T[c*FF + tid];
        float w1 = g_Wf1T[c*FF + tid + 256];
        const float4* hp = (const float4*)hs[c];
        float4 v0=hp[0], v1=hp[1], v2=hp[2], v3=hp[3];
        float hv[16] = {v0.x,v0.y,v0.z,v0.w, v1.x,v1.y,v1.z,v1.w,
                        v2.x,v2.y,v2.z,v2.w, v3.x,v3.y,v3.z,v3.w};
        #pragma unroll
        for (int m=0;m<16;m++){
            a0[m] = fmaf(w0, hv[m], a0[m]);
            a1[m] = fmaf(w1, hv[m], a1[m]);
        }
    }
    float b0 = bf1[tid], b1v = bf1[tid+256];
    #pragma unroll
    for (int m=0;m<16;m++){
        g_t512[(size_t)(pt0+m)*FF + tid]       = fmaxf(a0[m]+b0, 0.f);
        g_t512[(size_t)(pt0+m)*FF + tid + 256] = fmaxf(a1[m]+b1v, 0.f);
    }
}

// ---------------- FFN stage 2 + residual + transpose write ------------------
__global__ void __launch_bounds__(128) k_ffn2(const float* __restrict__ bf2, float* __restrict__ out){
    __shared__ float ts[FF][16];      // 32KB; reused as output staging
    int pt0 = blockIdx.x * 16;
    int b   = pt0 >> 11;
    int n0  = pt0 & (NN-1);
    int tid = threadIdx.x;
    for (int f=tid; f<FF*16; f+=128) ts[f&511][f>>9] = g_t512[(size_t)pt0*FF + f];
    __syncthreads();
    float acc[16];
    #pragma unroll
    for (int m=0;m<16;m++) acc[m]=0.f;
    for (int r=0;r<FF;r++){
        float w = g_Wf2T[r*CC + tid];
        const float4* tp = (const float4*)ts[r];
        float4 v0=tp[0], v1=tp[1], v2=tp[2], v3=tp[3];
        float tv[16] = {v0.x,v0.y,v0.z,v0.w, v1.x,v1.y,v1.z,v1.w,
                        v2.x,v2.y,v2.z,v2.w, v3.x,v3.y,v3.z,v3.w};
        #pragma unroll
        for (int m=0;m<16;m++) acc[m] = fmaf(w, tv[m], acc[m]);
    }
    float bo = bf2[tid];
    __syncthreads();
    float* os = &ts[0][0];            // 16*128 floats
    #pragma unroll
    for (int m=0;m<16;m++)
        os[m*CC + tid] = g_hnew[(size_t)(pt0+m)*CC + tid] + acc[m] + bo;
    __syncthreads();
    for (int f=tid; f<16*CC; f+=128){
        int o = f >> 4, m = f & 15;
        out[(size_t)b*CC*NN + (size_t)o*NN + n0 + m] = os[m*CC + o];
    }
}

// ---------------- launch ----------------------------------------------------
extern "C" void kernel_launch(void* const* d_in, const int* in_sizes, int n_in,
                              void* d_out, int out_size){
    const float* x    = (const float*)d_in[0];
    const float* p    = (const float*)d_in[1];
    const float* Win  = (const float*)d_in[2];
    const float* bin_ = (const float*)d_in[3];
    const float* Wq   = (const float*)d_in[4];
    const float* Wk   = (const float*)d_in[5];
    const float* Wv   = (const float*)d_in[6];
    const float* Wd1  = (const float*)d_in[7];
    const float* bd1  = (const float*)d_in[8];
    const float* Wd2  = (const float*)d_in[9];
    const float* bd2  = (const float*)d_in[10];
    const float* Wa   = (const float*)d_in[11];
    const float* ba   = (const float*)d_in[12];
    const float* g1   = (const float*)d_in[13];
    const float* b1   = (const float*)d_in[14];
    const float* g2   = (const float*)d_in[15];
    const float* b2   = (const float*)d_in[16];
    const float* Wf1  = (const float*)d_in[17];
    const float* bf1  = (const float*)d_in[18];
    const float* Wf2  = (const float*)d_in[19];
    const float* bf2  = (const float*)d_in[20];
    float* out = (float*)d_out;

    k_prep_tr<<<256, 256>>>(Win, Wd2, Wv, Wf1, Wf2);
    k_prep_combo<<<dim3(128,3), 128>>>(Wa, Wq, Wk, Wd2);
    k_prep_cd<<<1, 128>>>(Wa, bd2, ba);

    k_inproj<<<NP/16, 128>>>(x, bin_);
    {   // LN1: g_h -> g_hn
        float *hp, *hnp;
        cudaGetSymbolAddress((void**)&hp,  g_h);
        cudaGetSymbolAddress((void**)&hnp, g_hn);
        k_ln<<<NP, 128>>>(hp, hnp, g1, b1);
    }
    {   int* ip; cudaGetSymbolAddress((void**)&ip, g_idx);
        k_knn<<<NP, 256>>>(p, ip);
    }
    k_proj<<<NP/16, 128>>>();
    k_attn<<<NP, 128>>>(p, Wd1, bd1, bd2);
    {   // LN2: g_hnew -> g_h2
        float *hp, *h2p;
        cudaGetSymbolAddress((void**)&hp,  g_hnew);
        cudaGetSymbolAddress((void**)&h2p, g_h2);
        k_ln<<<NP, 128>>>(hp, h2p, g2, b2);
    }
    k_ffn1<<<NP/16, 256>>>(bf1);
    k_ffn2<<<NP/16, 128>>>(bf2, out);
}

// round 2
// speedup vs baseline: 1.0260x; 1.0260x over previous
#include <cuda_runtime.h>
#include <cuda_bf16.h>

// Problem constants (from reference setup_inputs)
#define BB 8
#define NN 2048
#define CIN 64
#define CC 128
#define KK 16
#define FF 512
#define NP (BB*NN)          // 16384 points

// ---------------- scratch (device globals; no cudaMalloc allowed) -----------
__device__ float g_h   [NP*CC];
__device__ float g_hn  [NP*CC];
__device__ float g_qa  [NP*CC];
__device__ float g_ka  [NP*CC];
__device__ float g_v   [NP*CC];
__device__ float g_hnew[NP*CC];
__device__ float g_h2  [NP*CC];
__device__ float g_t512[NP*FF];
__device__ int   g_idx [NP*KK];

__device__ float g_WinT[CIN*CC];      // [c][o]
__device__ float g_Wd2T[CC*CC];       // [c][o]
__device__ float g_WvT [CC*CC];       // [c][o]
__device__ float g_WaqT[CC*CC];       // (Wa@Wq) transposed: [c][o]
__device__ float g_WakT[CC*CC];       // (Wa@Wk) transposed
__device__ float g_WadT[CC*CC];       // (Wa@Wd2) transposed
__device__ float g_cd  [CC];          // Wa@bd2 + ba
__device__ float g_Wf1T[CC*FF];       // [c][r]
__device__ float g_Wf2T[FF*CC];       // [r][o]

// ---------------- f32x2 packed helpers --------------------------------------
__device__ __forceinline__ unsigned long long pack2(float x){
    unsigned long long r;
    asm("mov.b64 %0, {%1, %1};" : "=l"(r) : "f"(x));
    return r;
}
__device__ __forceinline__ void fma2(unsigned long long &a, unsigned long long b, unsigned long long c){
    asm("fma.rn.f32x2 %0, %1, %2, %0;" : "+l"(a) : "l"(b), "l"(c));
}
__device__ __forceinline__ float2 unpack2(unsigned long long v){
    float2 f;
    asm("mov.b64 {%0, %1}, %2;" : "=f"(f.x), "=f"(f.y) : "l"(v));
    return f;
}

// ---------------- prep: transposes ------------------------------------------
__global__ void k_prep_tr(const float* __restrict__ Win, const float* __restrict__ Wd2,
                          const float* __restrict__ Wv,  const float* __restrict__ Wf1,
                          const float* __restrict__ Wf2){
    int i = blockIdx.x*blockDim.x + threadIdx.x;   // 0..65535
    if (i < CIN*CC){ int c=i>>7, o=i&127; g_WinT[i] = Win[o*CIN+c]; }
    if (i < CC*CC){  int c=i>>7, o=i&127; g_Wd2T[i] = Wd2[o*CC+c]; g_WvT[i] = Wv[o*CC+c]; }
    if (i < CC*FF){  int c=i>>9, r=i&511; g_Wf1T[i] = Wf1[r*CC+c]; }
    if (i < FF*CC){  int r=i>>7, o=i&127; g_Wf2T[i] = Wf2[o*FF+r]; }
}

// ---------------- prep: combined weights (Wa@Wq etc.), stored transposed ----
__global__ void k_prep_combo(const float* __restrict__ Wa, const float* __restrict__ Wq,
                             const float* __restrict__ Wk, const float* __restrict__ Wd2){
    int o = blockIdx.x;          // 0..127
    int c = threadIdx.x;         // 0..127
    const float* src = (blockIdx.y==0)?Wq : (blockIdx.y==1)?Wk : Wd2;
    float* dst       = (blockIdx.y==0)?g_WaqT : (blockIdx.y==1)?g_WakT : g_WadT;
    float acc = 0.f;
    #pragma unroll 4
    for (int m=0; m<CC; m++) acc = fmaf(Wa[o*CC+m], src[m*CC+c], acc);
    dst[c*CC+o] = acc;
}

__global__ void k_prep_cd(const float* __restrict__ Wa, const float* __restrict__ bd2,
                          const float* __restrict__ ba){
    int o = threadIdx.x;
    float acc = ba[o];
    #pragma unroll 4
    for (int c=0;c<CC;c++) acc = fmaf(Wa[o*CC+c], bd2[c], acc);
    g_cd[o] = acc;
}

// ---------------- in_proj: h = Win @ x + bin  (16 points per block) ---------
__global__ void __launch_bounds__(128) k_inproj(const float* __restrict__ x,
                                                const float* __restrict__ binv){
    __shared__ __align__(16) float xs[CIN][16];
    int blk = blockIdx.x;                 // 0..1023
    int b   = blk >> 7;                   // 128 blocks per batch
    int n0  = (blk & 127) << 4;
    int pt0 = b*NN + n0;
    int tid = threadIdx.x;
    const float* xb = x + (size_t)b*CIN*NN;
    for (int f=tid; f<CIN*16; f+=128){ int c=f>>4, m=f&15; xs[c][m] = xb[c*NN + n0 + m]; }
    __syncthreads();
    unsigned long long acc[8];
    #pragma unroll
    for (int i=0;i<8;i++) acc[i]=0ull;
    #pragma unroll 2
    for (int c=0;c<CIN;c++){
        unsigned long long w2 = pack2(g_WinT[c*CC + tid]);
        const ulonglong2* xp = (const ulonglong2*)xs[c];
        ulonglong2 v0=xp[0], v1=xp[1], v2=xp[2], v3=xp[3];
        fma2(acc[0],w2,v0.x); fma2(acc[1],w2,v0.y);
        fma2(acc[2],w2,v1.x); fma2(acc[3],w2,v1.y);
        fma2(acc[4],w2,v2.x); fma2(acc[5],w2,v2.y);
        fma2(acc[6],w2,v3.x); fma2(acc[7],w2,v3.y);
    }
    float bo = binv[tid];
    #pragma unroll
    for (int i=0;i<8;i++){
        float2 f = unpack2(acc[i]);
        g_h[(size_t)(pt0+2*i)*CC   + tid] = f.x + bo;
        g_h[(size_t)(pt0+2*i+1)*CC + tid] = f.y + bo;
    }
}

// ---------------- LayerNorm over channels (block per point) -----------------
__global__ void __launch_bounds__(128) k_ln(const float* __restrict__ in, float* __restrict__ out,
                                            const float* __restrict__ g, const float* __restrict__ bbv){
    __shared__ float ws[4];
    int pt = blockIdx.x, t = threadIdx.x;
    float v = in[(size_t)pt*CC + t];
    float s = v;
    #pragma unroll
    for (int o=16;o;o>>=1) s += __shfl_xor_sync(0xffffffffu, s, o);
    if ((t&31)==0) ws[t>>5] = s;
    __syncthreads();
    float mu = (ws[0]+ws[1]+ws[2]+ws[3]) * (1.f/CC);
    float dv = v - mu;
    __syncthreads();
    float q = dv*dv;
    #pragma unroll
    for (int o=16;o;o>>=1) q += __shfl_xor_sync(0xffffffffu, q, o);
    if ((t&31)==0) ws[t>>5] = q;
    __syncthreads();
    float var = (ws[0]+ws[1]+ws[2]+ws[3]) * (1.f/CC);
    out[(size_t)pt*CC + t] = dv * rsqrtf(var + 1e-5f) * g[t] + bbv[t];
}

// ---------------- KNN: warp-per-query, register top-16 ----------------------
// key = ord(score)<<32 | ~idx  : larger key = nearer neighbor, tie -> smaller idx
__global__ void __launch_bounds__(512) k_knn(const float* __restrict__ p, int* __restrict__ idx_out){
    __shared__ float px[NN], py[NN], pz[NN], sw[NN];   // 32KB
    int blk = blockIdx.x;                 // 0..1023
    int b   = blk >> 7;
    int n0  = (blk & 127) << 4;
    int tid = threadIdx.x, lane = tid & 31, w = tid >> 5;
    const float* pb = p + (size_t)b*3*NN;
    for (int i=tid;i<NN;i+=512){
        float x=pb[i], y=pb[NN+i], z=pb[2*NN+i];
        px[i]=x; py[i]=y; pz[i]=z;
        sw[i]=x*x + y*y + z*z;
    }
    __syncthreads();
    int n = n0 + w;
    float qx=px[n], qy=py[n], qz=pz[n];
    float xxq = sw[n];
    float qx2 = 2.f*qx, qy2 = 2.f*qy, qz2 = 2.f*qz;
    unsigned long long t[16];
    #pragma unroll
    for (int a=0;a<16;a++) t[a]=0ull;
    #pragma unroll 4
    for (int i=lane;i<NN;i+=32){
        // s = -||q - p_i||^2 = 2*q.p_i - ||q||^2 - ||p_i||^2
        float s = fmaf(qx2, px[i], fmaf(qy2, py[i], fmaf(qz2, pz[i], -xxq - sw[i])));
        unsigned u = __float_as_uint(s);
        u ^= (u & 0x80000000u) ? 0xFFFFFFFFu : 0x80000000u;   // order-preserving map
        unsigned long long key = ((unsigned long long)u << 32) | (unsigned)(~i);
        if (i == n) key = 0ull;                                // exclude self
        if (key > t[15]){
            unsigned long long cur = key;
            #pragma unroll
            for (int a=0;a<16;a++){
                unsigned long long old = t[a];
                bool gt = cur > old;
                t[a] = gt ? cur : old;
                cur  = gt ? old : cur;
            }
        }
    }
    // merge 32 sorted lists: 16 rounds of warp max-extract
    unsigned long long head = t[0];
    unsigned myres = 0;
    #pragma unroll
    for (int r=0;r<16;r++){
        unsigned long long m = head;
        #pragma unroll
        for (int o=16;o;o>>=1){
            unsigned long long v = __shfl_xor_sync(0xffffffffu, m, o);
            if (v > m) m = v;
        }
        if (lane == r) myres = ~(unsigned)m;
        if (head == m){
            #pragma unroll
            for (int a=0;a<15;a++) t[a]=t[a+1];
            t[15]=0ull;
            head = t[0];
        }
    }
    if (lane < KK) idx_out[((size_t)b*NN + n)*KK + lane] = (int)myres;
}

// ---------------- projections: qa = hn@(WaWq)^T, ka = hn@(WaWk)^T, v = hn@Wv^T
__global__ void __launch_bounds__(128) k_proj(){
    __shared__ __align__(16) float hs[CC][16];
    int pt0 = blockIdx.x * 16;
    int tid = threadIdx.x;
    for (int f=tid; f<CC*16; f+=128) hs[f&127][f>>7] = g_hn[(size_t)pt0*CC + f];
    __syncthreads();
    unsigned long long aq[8], ak[8], av[8];
    #pragma unroll
    for (int i=0;i<8;i++){ aq[i]=0ull; ak[i]=0ull; av[i]=0ull; }
    for (int c=0;c<CC;c++){
        unsigned long long wq = pack2(g_WaqT[c*CC+tid]);
        unsigned long long wk = pack2(g_WakT[c*CC+tid]);
        unsigned long long wv = pack2(g_WvT [c*CC+tid]);
        const ulonglong2* hp = (const ulonglong2*)hs[c];
        ulonglong2 v0=hp[0], v1=hp[1], v2=hp[2], v3=hp[3];
        fma2(aq[0],wq,v0.x); fma2(aq[1],wq,v0.y); fma2(aq[2],wq,v1.x); fma2(aq[3],wq,v1.y);
        fma2(aq[4],wq,v2.x); fma2(aq[5],wq,v2.y); fma2(aq[6],wq,v3.x); fma2(aq[7],wq,v3.y);
        fma2(ak[0],wk,v0.x); fma2(ak[1],wk,v0.y); fma2(ak[2],wk,v1.x); fma2(ak[3],wk,v1.y);
        fma2(ak[4],wk,v2.x); fma2(ak[5],wk,v2.y); fma2(ak[6],wk,v3.x); fma2(ak[7],wk,v3.y);
        fma2(av[0],wv,v0.x); fma2(av[1],wv,v0.y); fma2(av[2],wv,v1.x); fma2(av[3],wv,v1.y);
        fma2(av[4],wv,v2.x); fma2(av[5],wv,v2.y); fma2(av[6],wv,v3.x); fma2(av[7],wv,v3.y);
    }
    #pragma unroll
    for (int i=0;i<8;i++){
        float2 fq = unpack2(aq[i]), fk = unpack2(ak[i]), fv = unpack2(av[i]);
        size_t b0 = (size_t)(pt0+2*i)*CC + tid;
        size_t b1 = (size_t)(pt0+2*i+1)*CC + tid;
        g_qa[b0]=fq.x; g_qa[b1]=fq.y;
        g_ka[b0]=fk.x; g_ka[b1]=fk.y;
        g_v [b0]=fv.x; g_v [b1]=fv.y;
    }
}

// ---------------- attention core (block per point, thread per channel) ------
__global__ void __launch_bounds__(128) k_attn(const float* __restrict__ p,
                                              const float* __restrict__ Wd1,
                                              const float* __restrict__ bd1,
                                              const float* __restrict__ bd2v){
    __shared__ __align__(16) float t_s[CC][16];
    __shared__ float rel_s[KK][3];
    __shared__ int   idxs[KK];
    int pt = blockIdx.x;
    int b  = pt >> 11;
    int n  = pt & (NN-1);
    int tid = threadIdx.x;
    if (tid < KK){
        int jn = g_idx[(size_t)pt*KK + tid];
        idxs[tid] = jn;
        const float* pb = p + (size_t)b*3*NN;
        rel_s[tid][0] = pb[n]        - pb[jn];
        rel_s[tid][1] = pb[NN+n]     - pb[NN+jn];
        rel_s[tid][2] = pb[2*NN+n]   - pb[2*NN+jn];
    }
    __syncthreads();
    {   // t_j[c] = relu(Wd1[c,:]·rel_j + bd1[c])
        float w0=Wd1[tid*3], w1=Wd1[tid*3+1], w2=Wd1[tid*3+2], bb=bd1[tid];
        #pragma unroll
        for (int j=0;j<KK;j++){
            float t = fmaf(w0, rel_s[j][0], fmaf(w1, rel_s[j][1], fmaf(w2, rel_s[j][2], bb)));
            t_s[tid][j] = fmaxf(t, 0.f);
        }
    }
    __syncthreads();
    unsigned long long dacc[8], lacc[8];
    #pragma unroll
    for (int i=0;i<8;i++){ dacc[i]=0ull; lacc[i]=0ull; }
    const float* wdp = g_Wd2T + tid;
    const float* wap = g_WadT + tid;
    #pragma unroll 2
    for (int c=0;c<CC;c++){
        unsigned long long wd2 = pack2(wdp[c*CC]);
        unsigned long long wa2 = pack2(wap[c*CC]);
        const ulonglong2* tp = (const ulonglong2*)t_s[c];
        ulonglong2 q0=tp[0], q1=tp[1], q2=tp[2], q3=tp[3];
        fma2(dacc[0],wd2,q0.x); fma2(dacc[1],wd2,q0.y);
        fma2(dacc[2],wd2,q1.x); fma2(dacc[3],wd2,q1.y);
        fma2(dacc[4],wd2,q2.x); fma2(dacc[5],wd2,q2.y);
        fma2(dacc[6],wd2,q3.x); fma2(dacc[7],wd2,q3.y);
        fma2(lacc[0],wa2,q0.x); fma2(lacc[1],wa2,q0.y);
        fma2(lacc[2],wa2,q1.x); fma2(lacc[3],wa2,q1.y);
        fma2(lacc[4],wa2,q2.x); fma2(lacc[5],wa2,q2.y);
        fma2(lacc[6],wa2,q3.x); fma2(lacc[7],wa2,q3.y);
    }
    float d[KK], l[KK];
    #pragma unroll
    for (int i=0;i<8;i++){
        float2 fd = unpack2(dacc[i]); d[2*i]=fd.x; d[2*i+1]=fd.y;
        float2 fl = unpack2(lacc[i]); l[2*i]=fl.x; l[2*i+1]=fl.y;
    }
    float bd2o = bd2v[tid];
    float base = g_qa[(size_t)pt*CC + tid] + g_cd[tid];
    float mx = -3.4e38f;
    #pragma unroll
    for (int j=0;j<KK;j++){
        l[j] += base - g_ka[((size_t)b*NN + idxs[j])*CC + tid];
        d[j] += bd2o;
        mx = fmaxf(mx, l[j]);
    }
    float s = 0.f;
    #pragma unroll
    for (int j=0;j<KK;j++){ l[j] = __expf(l[j]-mx); s += l[j]; }
    float y = 0.f;
    #pragma unroll
    for (int j=0;j<KK;j++){
        float vj = g_v[((size_t)b*NN + idxs[j])*CC + tid];
        y = fmaf(l[j], vj + d[j], y);
    }
    y /= s;
    g_hnew[(size_t)pt*CC + tid] = g_h[(size_t)pt*CC + tid] + y;
}

// ---------------- FFN stage 1: t = relu(h2 @ Wf1^T + bf1) -------------------
__global__ void __launch_bounds__(256) k_ffn1(const float* __restrict__ bf1){
    __shared__ __align__(16) float hs[CC][16];
    int pt0 = blockIdx.x * 16;
    int tid = threadIdx.x;
    for (int f=tid; f<CC*16; f+=256) hs[f&127][f>>7] = g_h2[(size_t)pt0*CC + f];
    __syncthreads();
    unsigned long long a0[8], a1[8];
    #pragma unroll
    for (int i=0;i<8;i++){ a0[i]=0ull; a1[i]=0ull; }
    for (int c=0;c<CC;c++){
        unsigned long long w0 = pack2(g_Wf1T[c*FF + tid]);
        unsigned long long w1 = pack2(g_Wf1T[c*FF + tid + 256]);
        const ulonglong2* hp = (const ulonglong2*)hs[c];
        ulonglong2 v0=hp[0], v1=hp[1], v2=hp[2], v3=hp[3];
        fma2(a0[0],w0,v0.x); fma2(a0[1],w0,v0.y); fma2(a0[2],w0,v1.x); fma2(a0[3],w0,v1.y);
        fma2(a0[4],w0,v2.x); fma2(a0[5],w0,v2.y); fma2(a0[6],w0,v3.x); fma2(a0[7],w0,v3.y);
        fma2(a1[0],w1,v0.x); fma2(a1[1],w1,v0.y); fma2(a1[2],w1,v1.x); fma2(a1[3],w1,v1.y);
        fma2(a1[4],w1,v2.x); fma2(a1[5],w1,v2.y); fma2(a1[6],w1,v3.x); fma2(a1[7],w1,v3.y);
    }
    float b0 = bf1[tid], b1v = bf1[tid+256];
    #pragma unroll
    for (int i=0;i<8;i++){
        float2 f0 = unpack2(a0[i]), f1 = unpack2(a1[i]);
        g_t512[(size_t)(pt0+2*i)*FF   + tid]       = fmaxf(f0.x+b0, 0.f);
        g_t512[(size_t)(pt0+2*i+1)*FF + tid]       = fmaxf(f0.y+b0, 0.f);
        g_t512[(size_t)(pt0+2*i)*FF   + tid + 256] = fmaxf(f1.x+b1v, 0.f);
        g_t512[(size_t)(pt0+2*i+1)*FF + tid + 256] = fmaxf(f1.y+b1v, 0.f);
    }
}

// ---------------- FFN stage 2 + residual + transpose write ------------------
__global__ void __launch_bounds__(128) k_ffn2(const float* __restrict__ bf2, float* __restrict__ out){
    __shared__ __align__(16) float ts[FF][16];      // 32KB; reused as output staging
    int pt0 = blockIdx.x * 16;
    int b   = pt0 >> 11;
    int n0  = pt0 & (NN-1);
    int tid = threadIdx.x;
    for (int f=tid; f<FF*16; f+=128) ts[f&511][f>>9] = g_t512[(size_t)pt0*FF + f];
    __syncthreads();
    unsigned long long acc[8];
    #pragma unroll
    for (int i=0;i<8;i++) acc[i]=0ull;
    #pragma unroll 2
    for (int r=0;r<FF;r++){
        unsigned long long w2 = pack2(g_Wf2T[r*CC + tid]);
        const ulonglong2* tp = (const ulonglong2*)ts[r];
        ulonglong2 v0=tp[0], v1=tp[1], v2=tp[2], v3=tp[3];
        fma2(acc[0],w2,v0.x); fma2(acc[1],w2,v0.y);
        fma2(acc[2],w2,v1.x); fma2(acc[3],w2,v1.y);
        fma2(acc[4],w2,v2.x); fma2(acc[5],w2,v2.y);
        fma2(acc[6],w2,v3.x); fma2(acc[7],w2,v3.y);
    }
    float bo = bf2[tid];
    float res[16];
    #pragma unroll
    for (int i=0;i<8;i++){
        float2 f = unpack2(acc[i]);
        res[2*i]   = g_hnew[(size_t)(pt0+2*i)*CC   + tid] + f.x + bo;
        res[2*i+1] = g_hnew[(size_t)(pt0+2*i+1)*CC + tid] + f.y + bo;
    }
    __syncthreads();
    float* os = &ts[0][0];            // 16*128 floats staging
    #pragma unroll
    for (int m=0;m<16;m++) os[m*CC + tid] = res[m];
    __syncthreads();
    for (int f=tid; f<16*CC; f+=128){
        int o = f >> 4, m = f & 15;
        out[(size_t)b*CC*NN + (size_t)o*NN + n0 + m] = os[m*CC + o];
    }
}

// ---------------- launch ----------------------------------------------------
extern "C" void kernel_launch(void* const* d_in, const int* in_sizes, int n_in,
                              void* d_out, int out_size){
    const float* x    = (const float*)d_in[0];
    const float* p    = (const float*)d_in[1];
    const float* Win  = (const float*)d_in[2];
    const float* bin_ = (const float*)d_in[3];
    const float* Wq   = (const float*)d_in[4];
    const float* Wk   = (const float*)d_in[5];
    const float* Wv   = (const float*)d_in[6];
    const float* Wd1  = (const float*)d_in[7];
    const float* bd1  = (const float*)d_in[8];
    const float* Wd2  = (const float*)d_in[9];
    const float* bd2  = (const float*)d_in[10];
    const float* Wa   = (const float*)d_in[11];
    const float* ba   = (const float*)d_in[12];
    const float* g1   = (const float*)d_in[13];
    const float* b1   = (const float*)d_in[14];
    const float* g2   = (const float*)d_in[15];
    const float* b2   = (const float*)d_in[16];
    const float* Wf1  = (const float*)d_in[17];
    const float* bf1  = (const float*)d_in[18];
    const float* Wf2  = (const float*)d_in[19];
    const float* bf2  = (const float*)d_in[20];
    float* out = (float*)d_out;

    k_prep_tr<<<256, 256>>>(Win, Wd2, Wv, Wf1, Wf2);
    k_prep_combo<<<dim3(128,3), 128>>>(Wa, Wq, Wk, Wd2);
    k_prep_cd<<<1, 128>>>(Wa, bd2, ba);

    k_inproj<<<NP/16, 128>>>(x, bin_);
    {   // LN1: g_h -> g_hn
        float *hp, *hnp;
        cudaGetSymbolAddress((void**)&hp,  g_h);
        cudaGetSymbolAddress((void**)&hnp, g_hn);
        k_ln<<<NP, 128>>>(hp, hnp, g1, b1);
    }
    {   int* ip; cudaGetSymbolAddress((void**)&ip, g_idx);
        k_knn<<<NP/16, 512>>>(p, ip);
    }
    k_proj<<<NP/16, 128>>>();
    k_attn<<<NP, 128>>>(p, Wd1, bd1, bd2);
    {   // LN2: g_hnew -> g_h2
        float *hp, *h2p;
        cudaGetSymbolAddress((void**)&hp,  g_hnew);
        cudaGetSymbolAddress((void**)&h2p, g_h2);
        k_ln<<<NP, 128>>>(hp, h2p, g2, b2);
    }
    k_ffn1<<<NP/16, 256>>>(bf1);
    k_ffn2<<<NP/16, 128>>>(bf2, out);
}

// round 3
// speedup vs baseline: 1.1684x; 1.1388x over previous
#include <cuda_runtime.h>
#include <cuda_bf16.h>

// Problem constants
#define BB 8
#define NN 2048
#define CIN 64
#define CC 128
#define KK 16
#define FF 512
#define NP (BB*NN)          // 16384 points
#define NR (NP*KK)          // 262144 t-rows

// ---------------- scratch ----------------------------------------------------
__device__ float g_h   [NP*CC];
__device__ float g_hn  [NP*CC];
__device__ float g_qa  [NP*CC];
__device__ float g_ka  [NP*CC];
__device__ float g_v   [NP*CC];
__device__ float g_hnew[NP*CC];
__device__ float g_h2  [NP*CC];
__device__ float g_t512[NP*FF];
__device__ int   g_idx [NP*KK];
__device__ float g_D   [(size_t)NR*256];     // GEMM output: [d-part | l-part]

__device__ float    g_WinT[CIN*CC];
__device__ float    g_WvT [CC*CC];
__device__ float    g_WaqT[CC*CC];
__device__ float    g_WakT[CC*CC];
__device__ float    g_cd  [CC];              // Wa@bd2 + ba
__device__ unsigned g_W2  [CC*256];          // tf32 bits: [c][0:128]=Wd2T, [c][128:256]=(WaWd2)T
__device__ float    g_Wf1T[CC*FF];
__device__ float    g_Wf2T[FF*CC];

// ---------------- helpers ----------------------------------------------------
__device__ __forceinline__ unsigned long long pack2(float x){
    unsigned long long r; asm("mov.b64 %0, {%1, %1};" : "=l"(r) : "f"(x)); return r;
}
__device__ __forceinline__ void fma2(unsigned long long &a, unsigned long long b, unsigned long long c){
    asm("fma.rn.f32x2 %0, %1, %2, %0;" : "+l"(a) : "l"(b), "l"(c));
}
__device__ __forceinline__ float2 unpack2(unsigned long long v){
    float2 f; asm("mov.b64 {%0, %1}, %2;" : "=f"(f.x), "=f"(f.y) : "l"(v)); return f;
}
__device__ __forceinline__ unsigned f2tf32(float f){
    unsigned u; asm("cvt.rna.tf32.f32 %0, %1;" : "=r"(u) : "f"(f)); return u;
}
__device__ __forceinline__ void mma_tf32(float* d, const unsigned* a, const unsigned* b){
    asm("mma.sync.aligned.m16n8k8.row.col.f32.tf32.tf32.f32 "
        "{%0,%1,%2,%3},{%4,%5,%6,%7},{%8,%9},{%0,%1,%2,%3};"
        : "+f"(d[0]),"+f"(d[1]),"+f"(d[2]),"+f"(d[3])
        : "r"(a[0]),"r"(a[1]),"r"(a[2]),"r"(a[3]), "r"(b[0]),"r"(b[1]));
}

// ---------------- prep kernels -----------------------------------------------
__global__ void k_prep_tr(const float* __restrict__ Win, const float* __restrict__ Wd2,
                          const float* __restrict__ Wv,  const float* __restrict__ Wf1,
                          const float* __restrict__ Wf2){
    int i = blockIdx.x*blockDim.x + threadIdx.x;   // 0..65535
    if (i < CIN*CC){ int c=i>>7, o=i&127; g_WinT[i] = Win[o*CIN+c]; }
    if (i < CC*CC){  int c=i>>7, o=i&127;
        float wd2 = Wd2[o*CC+c];
        g_W2[c*256+o] = f2tf32(wd2);
        g_WvT[i] = Wv[o*CC+c]; }
    if (i < CC*FF){  int c=i>>9, r=i&511; g_Wf1T[i] = Wf1[r*CC+c]; }
    if (i < FF*CC){  int r=i>>7, o=i&127; g_Wf2T[i] = Wf2[o*FF+r]; }
}

__global__ void k_prep_combo(const float* __restrict__ Wa, const float* __restrict__ Wq,
                             const float* __restrict__ Wk, const float* __restrict__ Wd2){
    int o = blockIdx.x;          // 0..127
    int c = threadIdx.x;         // 0..127
    const float* src = (blockIdx.y==0)?Wq : (blockIdx.y==1)?Wk : Wd2;
    float acc = 0.f;
    #pragma unroll 4
    for (int m=0; m<CC; m++) acc = fmaf(Wa[o*CC+m], src[m*CC+c], acc);
    if (blockIdx.y==0)      g_WaqT[c*CC+o] = acc;
    else if (blockIdx.y==1) g_WakT[c*CC+o] = acc;
    else                    g_W2[c*256+128+o] = f2tf32(acc);
}

__global__ void k_prep_cd(const float* __restrict__ Wa, const float* __restrict__ bd2,
                          const float* __restrict__ ba){
    int o = threadIdx.x;
    float acc = ba[o];
    #pragma unroll 4
    for (int c=0;c<CC;c++) acc = fmaf(Wa[o*CC+c], bd2[c], acc);
    g_cd[o] = acc;
}

// ---------------- in_proj ----------------------------------------------------
__global__ void __launch_bounds__(128) k_inproj(const float* __restrict__ x,
                                                const float* __restrict__ binv){
    __shared__ __align__(16) float xs[CIN][16];
    int blk = blockIdx.x;
    int b   = blk >> 7;
    int n0  = (blk & 127) << 4;
    int pt0 = b*NN + n0;
    int tid = threadIdx.x;
    const float* xb = x + (size_t)b*CIN*NN;
    for (int f=tid; f<CIN*16; f+=128){ int c=f>>4, m=f&15; xs[c][m] = xb[c*NN + n0 + m]; }
    __syncthreads();
    unsigned long long acc[8];
    #pragma unroll
    for (int i=0;i<8;i++) acc[i]=0ull;
    #pragma unroll 2
    for (int c=0;c<CIN;c++){
        unsigned long long w2 = pack2(g_WinT[c*CC + tid]);
        const ulonglong2* xp = (const ulonglong2*)xs[c];
        ulonglong2 v0=xp[0], v1=xp[1], v2=xp[2], v3=xp[3];
        fma2(acc[0],w2,v0.x); fma2(acc[1],w2,v0.y);
        fma2(acc[2],w2,v1.x); fma2(acc[3],w2,v1.y);
        fma2(acc[4],w2,v2.x); fma2(acc[5],w2,v2.y);
        fma2(acc[6],w2,v3.x); fma2(acc[7],w2,v3.y);
    }
    float bo = binv[tid];
    #pragma unroll
    for (int i=0;i<8;i++){
        float2 f = unpack2(acc[i]);
        g_h[(size_t)(pt0+2*i)*CC   + tid] = f.x + bo;
        g_h[(size_t)(pt0+2*i+1)*CC + tid] = f.y + bo;
    }
}

// ---------------- LayerNorm ---------------------------------------------------
__global__ void __launch_bounds__(128) k_ln(const float* __restrict__ in, float* __restrict__ out,
                                            const float* __restrict__ g, const float* __restrict__ bbv){
    __shared__ float ws[4];
    int pt = blockIdx.x, t = threadIdx.x;
    float v = in[(size_t)pt*CC + t];
    float s = v;
    #pragma unroll
    for (int o=16;o;o>>=1) s += __shfl_xor_sync(0xffffffffu, s, o);
    if ((t&31)==0) ws[t>>5] = s;
    __syncthreads();
    float mu = (ws[0]+ws[1]+ws[2]+ws[3]) * (1.f/CC);
    float dv = v - mu;
    __syncthreads();
    float q = dv*dv;
    #pragma unroll
    for (int o=16;o;o>>=1) q += __shfl_xor_sync(0xffffffffu, q, o);
    if ((t&31)==0) ws[t>>5] = q;
    __syncthreads();
    float var = (ws[0]+ws[1]+ws[2]+ws[3]) * (1.f/CC);
    out[(size_t)pt*CC + t] = dv * rsqrtf(var + 1e-5f) * g[t] + bbv[t];
}

// ---------------- KNN: warp-per-query, register top-16 ------------------------
__global__ void __launch_bounds__(512) k_knn(const float* __restrict__ p, int* __restrict__ idx_out){
    __shared__ float px[NN], py[NN], pz[NN], sw[NN];
    int blk = blockIdx.x;
    int b   = blk >> 7;
    int n0  = (blk & 127) << 4;
    int tid = threadIdx.x, lane = tid & 31, w = tid >> 5;
    const float* pb = p + (size_t)b*3*NN;
    for (int i=tid;i<NN;i+=512){
        float x=pb[i], y=pb[NN+i], z=pb[2*NN+i];
        px[i]=x; py[i]=y; pz[i]=z;
        sw[i]=x*x + y*y + z*z;
    }
    __syncthreads();
    int n = n0 + w;
    float qx=px[n], qy=py[n], qz=pz[n];
    float xxq = sw[n];
    float qx2 = 2.f*qx, qy2 = 2.f*qy, qz2 = 2.f*qz;
    unsigned long long t[16];
    #pragma unroll
    for (int a=0;a<16;a++) t[a]=0ull;
    #pragma unroll 4
    for (int i=lane;i<NN;i+=32){
        float s = fmaf(qx2, px[i], fmaf(qy2, py[i], fmaf(qz2, pz[i], -xxq - sw[i])));
        unsigned u = __float_as_uint(s);
        u ^= (u & 0x80000000u) ? 0xFFFFFFFFu : 0x80000000u;
        unsigned long long key = ((unsigned long long)u << 32) | (unsigned)(~i);
        if (i == n) key = 0ull;
        if (key > t[15]){
            unsigned long long cur = key;
            #pragma unroll
            for (int a=0;a<16;a++){
                unsigned long long old = t[a];
                bool gt = cur > old;
                t[a] = gt ? cur : old;
                cur  = gt ? old : cur;
            }
        }
    }
    unsigned long long head = t[0];
    unsigned myres = 0;
    #pragma unroll
    for (int r=0;r<16;r++){
        unsigned long long m = head;
        #pragma unroll
        for (int o=16;o;o>>=1){
            unsigned long long v = __shfl_xor_sync(0xffffffffu, m, o);
            if (v > m) m = v;
        }
        if (lane == r) myres = ~(unsigned)m;
        if (head == m){
            #pragma unroll
            for (int a=0;a<15;a++) t[a]=t[a+1];
            t[15]=0ull;
            head = t[0];
        }
    }
    if (lane < KK) idx_out[((size_t)b*NN + n)*KK + lane] = (int)myres;
}

// ---------------- projections -------------------------------------------------
__global__ void __launch_bounds__(128) k_proj(){
    __shared__ __align__(16) float hs[CC][16];
    int pt0 = blockIdx.x * 16;
    int tid = threadIdx.x;
    for (int f=tid; f<CC*16; f+=128) hs[f&127][f>>7] = g_hn[(size_t)pt0*CC + f];
    __syncthreads();
    unsigned long long aq[8], ak[8], av[8];
    #pragma unroll
    for (int i=0;i<8;i++){ aq[i]=0ull; ak[i]=0ull; av[i]=0ull; }
    for (int c=0;c<CC;c++){
        unsigned long long wq = pack2(g_WaqT[c*CC+tid]);
        unsigned long long wk = pack2(g_WakT[c*CC+tid]);
        unsigned long long wv = pack2(g_WvT [c*CC+tid]);
        const ulonglong2* hp = (const ulonglong2*)hs[c];
        ulonglong2 v0=hp[0], v1=hp[1], v2=hp[2], v3=hp[3];
        fma2(aq[0],wq,v0.x); fma2(aq[1],wq,v0.y); fma2(aq[2],wq,v1.x); fma2(aq[3],wq,v1.y);
        fma2(aq[4],wq,v2.x); fma2(aq[5],wq,v2.y); fma2(aq[6],wq,v3.x); fma2(aq[7],wq,v3.y);
        fma2(ak[0],wk,v0.x); fma2(ak[1],wk,v0.y); fma2(ak[2],wk,v1.x); fma2(ak[3],wk,v1.y);
        fma2(ak[4],wk,v2.x); fma2(ak[5],wk,v2.y); fma2(ak[6],wk,v3.x); fma2(ak[7],wk,v3.y);
        fma2(av[0],wv,v0.x); fma2(av[1],wv,v0.y); fma2(av[2],wv,v1.x); fma2(av[3],wv,v1.y);
        fma2(av[4],wv,v2.x); fma2(av[5],wv,v2.y); fma2(av[6],wv,v3.x); fma2(av[7],wv,v3.y);
    }
    #pragma unroll
    for (int i=0;i<8;i++){
        float2 fq = unpack2(aq[i]), fk = unpack2(ak[i]), fv = unpack2(av[i]);
        size_t b0 = (size_t)(pt0+2*i)*CC + tid;
        size_t b1 = (size_t)(pt0+2*i+1)*CC + tid;
        g_qa[b0]=fq.x; g_qa[b1]=fq.y;
        g_ka[b0]=fk.x; g_ka[b1]=fk.y;
        g_v [b0]=fv.x; g_v [b1]=fv.y;
    }
}

// ---------------- attention GEMM: D[NR x 256] = relu(rel@Wd1^T+bd1) @ W2 -----
// tf32 mma.sync, block tile 128x128, warp tile 64x32 (2x4 warps), K=128.
// A tile computed in-place from geometry (fused t-matrix build).
__global__ void __launch_bounds__(256) k_attn_gemm(const float* __restrict__ p,
                                                   const float* __restrict__ Wd1,
                                                   const float* __restrict__ bd1){
    extern __shared__ unsigned As[];          // [128][132] tf32 bits
    __shared__ float wd1s[CC][3];
    __shared__ float bd1s[CC];
    __shared__ float rel3[128][3];
    int tid  = threadIdx.x;
    int mtile = blockIdx.x;                   // 0..2047  (8 points each)
    int ntile = blockIdx.y;                   // 0..1
    int pt0 = mtile*8;

    if (tid < CC){
        wd1s[tid][0]=Wd1[tid*3]; wd1s[tid][1]=Wd1[tid*3+1]; wd1s[tid][2]=Wd1[tid*3+2];
        bd1s[tid]=bd1[tid];
    }
    if (tid < 128){
        int row = tid;
        int pt  = pt0 + (row>>4);
        int j   = row & 15;
        int b   = pt >> 11, n = pt & (NN-1);
        int jn  = g_idx[(size_t)pt*KK + j];
        const float* pb = p + (size_t)b*3*NN;
        rel3[row][0] = pb[n]      - pb[jn];
        rel3[row][1] = pb[NN+n]   - pb[NN+jn];
        rel3[row][2] = pb[2*NN+n] - pb[2*NN+jn];
    }
    __syncthreads();
    // build A tile (tf32): As[row][c] = relu(Wd1[c]·rel[row] + bd1[c])
    for (int e=tid; e<128*128; e+=256){
        int row = e >> 7, c = e & 127;
        float t = fmaf(wd1s[c][0], rel3[row][0],
                  fmaf(wd1s[c][1], rel3[row][1],
                  fmaf(wd1s[c][2], rel3[row][2], bd1s[c])));
        As[row*132 + c] = f2tf32(fmaxf(t, 0.f));
    }
    __syncthreads();

    int wid = tid >> 5, lane = tid & 31;
    int wm = wid & 1, wn = wid >> 1;          // 2 x 4 warp grid
    int g  = lane >> 2, tg = lane & 3;
    float acc[4][4][4];
    #pragma unroll
    for (int mi=0;mi<4;mi++)
        #pragma unroll
        for (int ni=0;ni<4;ni++)
            #pragma unroll
            for (int q=0;q<4;q++) acc[mi][ni][q]=0.f;

    const unsigned* W2 = g_W2;
    int cbase = ntile*128 + wn*32;
    for (int ks=0; ks<16; ks++){
        int k = ks*8;
        unsigned afr[4][4];
        #pragma unroll
        for (int mi=0;mi<4;mi++){
            int rb = wm*64 + mi*16;
            afr[mi][0] = As[(rb+g   )*132 + k + tg  ];
            afr[mi][1] = As[(rb+g+8 )*132 + k + tg  ];
            afr[mi][2] = As[(rb+g   )*132 + k + tg+4];
            afr[mi][3] = As[(rb+g+8 )*132 + k + tg+4];
        }
        unsigned bfr[4][2];
        #pragma unroll
        for (int ni=0;ni<4;ni++){
            int cb = cbase + ni*8 + g;
            bfr[ni][0] = W2[(k+tg  )*256 + cb];
            bfr[ni][1] = W2[(k+tg+4)*256 + cb];
        }
        #pragma unroll
        for (int mi=0;mi<4;mi++)
            #pragma unroll
            for (int ni=0;ni<4;ni++)
                mma_tf32(acc[mi][ni], afr[mi], bfr[ni]);
    }
    // epilogue
    #pragma unroll
    for (int mi=0;mi<4;mi++){
        int r0 = mtile*128 + wm*64 + mi*16 + g;
        #pragma unroll
        for (int ni=0;ni<4;ni++){
            int c0 = cbase + ni*8 + 2*tg;
            float2* d0 = (float2*)&g_D[(size_t)r0*256 + c0];
            *d0 = make_float2(acc[mi][ni][0], acc[mi][ni][1]);
            float2* d1 = (float2*)&g_D[(size_t)(r0+8)*256 + c0];
            *d1 = make_float2(acc[mi][ni][2], acc[mi][ni][3]);
        }
    }
}

// ---------------- attention finish: softmax + combine ------------------------
__global__ void __launch_bounds__(128) k_finish(const float* __restrict__ bd2v){
    __shared__ int idxs[KK];
    int pt = blockIdx.x;
    int b  = pt >> 11;
    int tid = threadIdx.x;
    if (tid < KK) idxs[tid] = g_idx[(size_t)pt*KK + tid];
    __syncthreads();
    float bd2o = bd2v[tid];
    float base = g_qa[(size_t)pt*CC + tid] + g_cd[tid];
    float d[KK], l[KK];
    float mx = -3.4e38f;
    #pragma unroll
    for (int j=0;j<KK;j++){
        size_t r = (size_t)pt*KK + j;
        d[j] = g_D[r*256 + tid] + bd2o;
        l[j] = g_D[r*256 + 128 + tid] + base - g_ka[((size_t)b*NN + idxs[j])*CC + tid];
        mx = fmaxf(mx, l[j]);
    }
    float s = 0.f;
    #pragma unroll
    for (int j=0;j<KK;j++){ l[j] = __expf(l[j]-mx); s += l[j]; }
    float y = 0.f;
    #pragma unroll
    for (int j=0;j<KK;j++){
        float vj = g_v[((size_t)b*NN + idxs[j])*CC + tid];
        y = fmaf(l[j], vj + d[j], y);
    }
    y /= s;
    g_hnew[(size_t)pt*CC + tid] = g_h[(size_t)pt*CC + tid] + y;
}

// ---------------- FFN stage 1 -------------------------------------------------
__global__ void __launch_bounds__(256) k_ffn1(const float* __restrict__ bf1){
    __shared__ __align__(16) float hs[CC][16];
    int pt0 = blockIdx.x * 16;
    int tid = threadIdx.x;
    for (int f=tid; f<CC*16; f+=256) hs[f&127][f>>7] = g_h2[(size_t)pt0*CC + f];
    __syncthreads();
    unsigned long long a0[8], a1[8];
    #pragma unroll
    for (int i=0;i<8;i++){ a0[i]=0ull; a1[i]=0ull; }
    for (int c=0;c<CC;c++){
        unsigned long long w0 = pack2(g_Wf1T[c*FF + tid]);
        unsigned long long w1 = pack2(g_Wf1T[c*FF + tid + 256]);
        const ulonglong2* hp = (const ulonglong2*)hs[c];
        ulonglong2 v0=hp[0], v1=hp[1], v2=hp[2], v3=hp[3];
        fma2(a0[0],w0,v0.x); fma2(a0[1],w0,v0.y); fma2(a0[2],w0,v1.x); fma2(a0[3],w0,v1.y);
        fma2(a0[4],w0,v2.x); fma2(a0[5],w0,v2.y); fma2(a0[6],w0,v3.x); fma2(a0[7],w0,v3.y);
        fma2(a1[0],w1,v0.x); fma2(a1[1],w1,v0.y); fma2(a1[2],w1,v1.x); fma2(a1[3],w1,v1.y);
        fma2(a1[4],w1,v2.x); fma2(a1[5],w1,v2.y); fma2(a1[6],w1,v3.x); fma2(a1[7],w1,v3.y);
    }
    float b0 = bf1[tid], b1v = bf1[tid+256];
    #pragma unroll
    for (int i=0;i<8;i++){
        float2 f0 = unpack2(a0[i]), f1 = unpack2(a1[i]);
        g_t512[(size_t)(pt0+2*i)*FF   + tid]       = fmaxf(f0.x+b0, 0.f);
        g_t512[(size_t)(pt0+2*i+1)*FF + tid]       = fmaxf(f0.y+b0, 0.f);
        g_t512[(size_t)(pt0+2*i)*FF   + tid + 256] = fmaxf(f1.x+b1v, 0.f);
        g_t512[(size_t)(pt0+2*i+1)*FF + tid + 256] = fmaxf(f1.y+b1v, 0.f);
    }
}

// ---------------- FFN stage 2 + residual + transpose --------------------------
__global__ void __launch_bounds__(128) k_ffn2(const float* __restrict__ bf2, float* __restrict__ out){
    __shared__ __align__(16) float ts[FF][16];
    int pt0 = blockIdx.x * 16;
    int b   = pt0 >> 11;
    int n0  = pt0 & (NN-1);
    int tid = threadIdx.x;
    for (int f=tid; f<FF*16; f+=128) ts[f&511][f>>9] = g_t512[(size_t)pt0*FF + f];
    __syncthreads();
    unsigned long long acc[8];
    #pragma unroll
    for (int i=0;i<8;i++) acc[i]=0ull;
    #pragma unroll 2
    for (int r=0;r<FF;r++){
        unsigned long long w2 = pack2(g_Wf2T[r*CC + tid]);
        const ulonglong2* tp = (const ulonglong2*)ts[r];
        ulonglong2 v0=tp[0], v1=tp[1], v2=tp[2], v3=tp[3];
        fma2(acc[0],w2,v0.x); fma2(acc[1],w2,v0.y);
        fma2(acc[2],w2,v1.x); fma2(acc[3],w2,v1.y);
        fma2(acc[4],w2,v2.x); fma2(acc[5],w2,v2.y);
        fma2(acc[6],w2,v3.x); fma2(acc[7],w2,v3.y);
    }
    float bo = bf2[tid];
    float res[16];
    #pragma unroll
    for (int i=0;i<8;i++){
        float2 f = unpack2(acc[i]);
        res[2*i]   = g_hnew[(size_t)(pt0+2*i)*CC   + tid] + f.x + bo;
        res[2*i+1] = g_hnew[(size_t)(pt0+2*i+1)*CC + tid] + f.y + bo;
    }
    __syncthreads();
    float* os = &ts[0][0];
    #pragma unroll
    for (int m=0;m<16;m++) os[m*CC + tid] = res[m];
    __syncthreads();
    for (int f=tid; f<16*CC; f+=128){
        int o = f >> 4, m = f & 15;
        out[(size_t)b*CC*NN + (size_t)o*NN + n0 + m] = os[m*CC + o];
    }
}

// ---------------- launch ------------------------------------------------------
extern "C" void kernel_launch(void* const* d_in, const int* in_sizes, int n_in,
                              void* d_out, int out_size){
    const float* x    = (const float*)d_in[0];
    const float* p    = (const float*)d_in[1];
    const float* Win  = (const float*)d_in[2];
    const float* bin_ = (const float*)d_in[3];
    const float* Wq   = (const float*)d_in[4];
    const float* Wk   = (const float*)d_in[5];
    const float* Wv   = (const float*)d_in[6];
    const float* Wd1  = (const float*)d_in[7];
    const float* bd1  = (const float*)d_in[8];
    const float* Wd2  = (const float*)d_in[9];
    const float* bd2  = (const float*)d_in[10];
    const float* Wa   = (const float*)d_in[11];
    const float* ba   = (const float*)d_in[12];
    const float* g1   = (const float*)d_in[13];
    const float* b1   = (const float*)d_in[14];
    const float* g2   = (const float*)d_in[15];
    const float* b2   = (const float*)d_in[16];
    const float* Wf1  = (const float*)d_in[17];
    const float* bf1  = (const float*)d_in[18];
    const float* Wf2  = (const float*)d_in[19];
    const float* bf2  = (const float*)d_in[20];
    float* out = (float*)d_out;

    const int GEMM_SMEM = 128*132*4;   // 67584
    cudaFuncSetAttribute(k_attn_gemm, cudaFuncAttributeMaxDynamicSharedMemorySize, GEMM_SMEM);

    k_prep_tr<<<256, 256>>>(Win, Wd2, Wv, Wf1, Wf2);
    k_prep_combo<<<dim3(128,3), 128>>>(Wa, Wq, Wk, Wd2);
    k_prep_cd<<<1, 128>>>(Wa, bd2, ba);

    k_inproj<<<NP/16, 128>>>(x, bin_);
    {
        float *hp, *hnp;
        cudaGetSymbolAddress((void**)&hp,  g_h);
        cudaGetSymbolAddress((void**)&hnp, g_hn);
        k_ln<<<NP, 128>>>(hp, hnp, g1, b1);
    }
    {
        int* ip; cudaGetSymbolAddress((void**)&ip, g_idx);
        k_knn<<<NP/16, 512>>>(p, ip);
    }
    k_proj<<<NP/16, 128>>>();
    k_attn_gemm<<<dim3(NR/128, 2), 256, GEMM_SMEM>>>(p, Wd1, bd1);
    k_finish<<<NP, 128>>>(bd2);
    {
        float *hp, *h2p;
        cudaGetSymbolAddress((void**)&hp,  g_hnew);
        cudaGetSymbolAddress((void**)&h2p, g_h2);
        k_ln<<<NP, 128>>>(hp, h2p, g2, b2);
    }
    k_ffn1<<<NP/16, 256>>>(bf1);
    k_ffn2<<<NP/16, 128>>>(bf2, out);
}